// round 4
// baseline (speedup 1.0000x reference)
#include <cuda_runtime.h>
#include <cuda_bf16.h>
#include <math.h>

// ---------------------------------------------------------------------------
// Problem constants
//   B=16, C=3, H=W=512, P=16  -> 32x32=1024 patches/img, 16384 tokens total
//   D=768, F=3072, NH=12, dh=64, WIN=64  -> 16 windows/img, 256 windows total
// ---------------------------------------------------------------------------
#define MTOK   16384
#define DMODEL 768
#define FFDIM  3072
#define QKVDIM 2304

// ------------------------- scratch (device globals) ------------------------
__device__ float g_x[MTOK * DMODEL];     // LN+PE output (identity #1)
__device__ float g_y[MTOK * DMODEL];     // ff out / attn out
__device__ float g_z[MTOK * DMODEL];     // post-attn (identity #2)
__device__ float g_h[MTOK * FFDIM];      // im2col buffer, then FF hidden
__device__ float g_qkv[MTOK * QKVDIM];
__device__ float g_wT[DMODEL * DMODEL];  // patch_w transposed to [K x D]
__device__ float g_invfreq[DMODEL / 2];  // PE frequency table

// ------------------------------- helpers -----------------------------------
__device__ __forceinline__ float gelu_tanh(float x) {
    // jax.nn.gelu default (approximate=True)
    float x3 = x * x * x;
    return 0.5f * x * (1.f + tanhf(0.7978845608028654f * (x + 0.044715f * x3)));
}

// ---------------------------- PE freq table ---------------------------------
__global__ void build_invfreq_kernel(float* inv) {
    int i = blockIdx.x * blockDim.x + threadIdx.x;
    if (i < DMODEL / 2) {
        inv[i] = (float)exp(-(double)i * (2.0 / (double)DMODEL) * log(10000.0));
    }
}

// --------------------------- transpose patch_w ------------------------------
// patch_w: [D, C*P*P] = [768, 768] row-major  ->  wT[k*768 + d]
__global__ void transpose_pw_kernel(const float* __restrict__ w,
                                    float* __restrict__ wT) {
    int idx = blockIdx.x * blockDim.x + threadIdx.x;   // 768*768
    if (idx < DMODEL * DMODEL) {
        int d = idx / DMODEL, k = idx % DMODEL;
        wT[k * DMODEL + d] = w[idx];
    }
}

// -------------------------------- im2col ------------------------------------
// A[m, k] with m = b*1024 + hp*32 + wp, k = c*256 + p*16 + q
// A[m,k] = input[b, c, hp*16+p, wp*16+q]; float4 over q.
__global__ void im2col_kernel(const float* __restrict__ in,
                              float* __restrict__ A) {
    int idx = blockIdx.x * blockDim.x + threadIdx.x;   // MTOK*768/4 units
    int m  = idx / 192;
    int k  = (idx % 192) * 4;
    int b  = m >> 10;
    int n  = m & 1023;
    int hp = n >> 5, wp = n & 31;
    int c   = k >> 8;
    int rem = k & 255;
    int p = rem >> 4, q = rem & 15;
    const float* src = in + ((((size_t)b * 3 + c) * 512) + (size_t)hp * 16 + p) * 512
                          + (size_t)wp * 16 + q;
    *reinterpret_cast<float4*>(&A[(size_t)m * DMODEL + k]) =
        *reinterpret_cast<const float4*>(src);
}

// --------------------------- LayerNorm + PE ---------------------------------
__global__ void ln_pe_kernel(const float* __restrict__ x,
                             const float* __restrict__ gam,
                             const float* __restrict__ bet,
                             const float* __restrict__ invfreq,
                             float* __restrict__ out) {
    __shared__ float ss[8], sq[8];
    int m = blockIdx.x;
    int t = threadIdx.x;                 // 256 threads
    const float* row = x + (size_t)m * DMODEL;
    float v0 = row[t], v1 = row[t + 256], v2 = row[t + 512];
    float s = v0 + v1 + v2;
    float q = v0 * v0 + v1 * v1 + v2 * v2;
    #pragma unroll
    for (int o = 16; o > 0; o >>= 1) {
        s += __shfl_down_sync(0xFFFFFFFFu, s, o);
        q += __shfl_down_sync(0xFFFFFFFFu, q, o);
    }
    int warp = t >> 5, lane = t & 31;
    if (lane == 0) { ss[warp] = s; sq[warp] = q; }
    __syncthreads();
    if (t == 0) {
        float S = 0.f, Q = 0.f;
        #pragma unroll
        for (int i = 0; i < 8; i++) { S += ss[i]; Q += sq[i]; }
        float mean = S * (1.f / 768.f);
        float var  = Q * (1.f / 768.f) - mean * mean;
        ss[0] = mean;
        sq[0] = rsqrtf(var + 1e-5f);
    }
    __syncthreads();
    float mean = ss[0], rstd = sq[0];
    int n = m & 1023;
    float vals[3] = {v0, v1, v2};
    #pragma unroll
    for (int e = 0; e < 3; e++) {
        int d = t + e * 256;
        float ang = (float)n * invfreq[d >> 1];
        float pe  = (d & 1) ? cosf(ang) : sinf(ang);
        out[(size_t)m * DMODEL + d] = (vals[e] - mean) * rstd * gam[d] + bet[d] + pe;
    }
}

// ------------------------------ SGEMM ---------------------------------------
// C[M,N] = A[M,K] @ B[K,N] + bias[N]  (+GELU) (+res[M,N])
// 128x128 block tile, K-step 8, 256 threads, 8x8 per thread as two 4-chunks.
// Requires M%128==0, N%128==0, K%8==0.
template <bool GELU, bool RES>
__global__ __launch_bounds__(256, 2)
void sgemm_kernel(const float* __restrict__ A, const float* __restrict__ B,
                  const float* __restrict__ bias, const float* __restrict__ res,
                  float* __restrict__ C, int M, int N, int K) {
    __shared__ float As[8][128];
    __shared__ float Bs[8][128];

    const int tid = threadIdx.x;
    const int m0 = blockIdx.y * 128;
    const int n0 = blockIdx.x * 128;
    const int tx = tid & 15;
    const int ty = tid >> 4;

    // global->smem load mapping
    const int ar = tid >> 1;            // 0..127 (A tile row)
    const int ac = (tid & 1) * 4;       // 0 or 4 (A tile k)
    const int br = tid >> 5;            // 0..7   (B tile k)
    const int bc = (tid & 31) * 4;      // 0..124 (B tile col)

    float acc[8][8];
    #pragma unroll
    for (int i = 0; i < 8; i++)
        #pragma unroll
        for (int j = 0; j < 8; j++) acc[i][j] = 0.f;

    // prologue prefetch
    float4 a4 = *reinterpret_cast<const float4*>(&A[(size_t)(m0 + ar) * K + ac]);
    float4 b4 = *reinterpret_cast<const float4*>(&B[(size_t)br * N + n0 + bc]);

    for (int k0 = 0; k0 < K; k0 += 8) {
        __syncthreads();
        As[ac + 0][ar] = a4.x;
        As[ac + 1][ar] = a4.y;
        As[ac + 2][ar] = a4.z;
        As[ac + 3][ar] = a4.w;
        *reinterpret_cast<float4*>(&Bs[br][bc]) = b4;
        __syncthreads();

        if (k0 + 8 < K) {
            a4 = *reinterpret_cast<const float4*>(&A[(size_t)(m0 + ar) * K + (k0 + 8) + ac]);
            b4 = *reinterpret_cast<const float4*>(&B[(size_t)(k0 + 8 + br) * N + n0 + bc]);
        }

        #pragma unroll
        for (int kk = 0; kk < 8; kk++) {
            float4 A0 = *reinterpret_cast<const float4*>(&As[kk][ty * 4]);
            float4 A1 = *reinterpret_cast<const float4*>(&As[kk][64 + ty * 4]);
            float4 B0 = *reinterpret_cast<const float4*>(&Bs[kk][tx * 4]);
            float4 B1 = *reinterpret_cast<const float4*>(&Bs[kk][64 + tx * 4]);
            float a[8] = {A0.x, A0.y, A0.z, A0.w, A1.x, A1.y, A1.z, A1.w};
            float b[8] = {B0.x, B0.y, B0.z, B0.w, B1.x, B1.y, B1.z, B1.w};
            #pragma unroll
            for (int i = 0; i < 8; i++)
                #pragma unroll
                for (int j = 0; j < 8; j++)
                    acc[i][j] += a[i] * b[j];
        }
    }

    // epilogue
    #pragma unroll
    for (int i = 0; i < 8; i++) {
        int m = m0 + ((i < 4) ? (ty * 4 + i) : (64 + ty * 4 + (i - 4)));
        size_t rowoff = (size_t)m * N;
        #pragma unroll
        for (int jg = 0; jg < 2; jg++) {
            int n = n0 + jg * 64 + tx * 4;
            float r[4];
            #pragma unroll
            for (int j = 0; j < 4; j++) {
                float v = acc[i][jg * 4 + j] + bias[n + j];
                if (GELU) v = gelu_tanh(v);
                r[j] = v;
            }
            if (RES) {
                float4 rv = *reinterpret_cast<const float4*>(&res[rowoff + n]);
                r[0] += rv.x; r[1] += rv.y; r[2] += rv.z; r[3] += rv.w;
            }
            float4 ov = make_float4(r[0], r[1], r[2], r[3]);
            *reinterpret_cast<float4*>(&C[rowoff + n]) = ov;
        }
    }
}

// --------------------------- window attention -------------------------------
// One block per (window, head). 256 windows x 12 heads = 3072 blocks.
// qkv row layout: [q(768) | k(768) | v(768)], col within = h*64 + d.
__global__ __launch_bounds__(256)
void attn_kernel(const float* __restrict__ qkv, float* __restrict__ o) {
    __shared__ float sA[64 * 64];   // Q, then V
    __shared__ float sK[64 * 64];
    __shared__ float sS[64 * 64];

    int wh = blockIdx.x;
    int h  = wh % 12;
    int w  = wh / 12;
    int m0 = (w >> 4) * 1024 + (w & 15) * 64;   // b*1024 + win*64

    int tid  = threadIdx.x;
    int lane = tid & 31;
    const float* base = qkv + (size_t)m0 * QKVDIM;
    int qoff = h * 64, koff = 768 + h * 64, voff = 1536 + h * 64;

    // load Q, K
    for (int u = tid; u < 1024; u += 256) {
        int r = u >> 4;
        int c4 = (u & 15) << 2;
        *reinterpret_cast<float4*>(&sA[r * 64 + c4]) =
            *reinterpret_cast<const float4*>(&base[(size_t)r * QKVDIM + qoff + c4]);
        *reinterpret_cast<float4*>(&sK[r * 64 + c4]) =
            *reinterpret_cast<const float4*>(&base[(size_t)r * QKVDIM + koff + c4]);
    }
    __syncthreads();

    // S = Q K^T * 0.125, 4x4 microtile, lane-skewed k (bank-conflict-free)
    int i0 = (tid >> 4) << 2;
    int j0 = (tid & 15) << 2;
    {
        float accS[4][4] = {};
        for (int kk = 0; kk < 64; kk++) {
            int ke = (kk + lane) & 63;
            float a[4], b[4];
            #pragma unroll
            for (int ii = 0; ii < 4; ii++) a[ii] = sA[(i0 + ii) * 64 + ke];
            #pragma unroll
            for (int jj = 0; jj < 4; jj++) b[jj] = sK[(j0 + jj) * 64 + ke];
            #pragma unroll
            for (int ii = 0; ii < 4; ii++)
                #pragma unroll
                for (int jj = 0; jj < 4; jj++)
                    accS[ii][jj] += a[ii] * b[jj];
        }
        #pragma unroll
        for (int ii = 0; ii < 4; ii++)
            #pragma unroll
            for (int jj = 0; jj < 4; jj++)
                sS[(i0 + ii) * 64 + (j0 + jj)] = accS[ii][jj] * 0.125f;
    }
    __syncthreads();   // S complete; Q (sA) now dead

    // softmax per row (threads 0..63, skewed column order)
    if (tid < 64) {
        int i = tid;
        float mx = -1e30f;
        for (int j = 0; j < 64; j++) {
            float s = sS[i * 64 + ((j + tid) & 63)];
            mx = fmaxf(mx, s);
        }
        float sum = 0.f;
        for (int j = 0; j < 64; j++) {
            int jj = (j + tid) & 63;
            float e = expf(sS[i * 64 + jj] - mx);
            sS[i * 64 + jj] = e;
            sum += e;
        }
        float invs = 1.f / sum;
        for (int j = 0; j < 64; j++) {
            int jj = (j + tid) & 63;
            sS[i * 64 + jj] *= invs;
        }
    }
    // load V into sA (Q region) — safe: all reads of Q done before prior sync
    for (int u = tid; u < 1024; u += 256) {
        int r = u >> 4;
        int c4 = (u & 15) << 2;
        *reinterpret_cast<float4*>(&sA[r * 64 + c4]) =
            *reinterpret_cast<const float4*>(&base[(size_t)r * QKVDIM + voff + c4]);
    }
    __syncthreads();

    // O = A @ V, 4x4 microtile over (i, d), lane-skewed j
    int d0 = j0;
    float accO[4][4] = {};
    for (int j = 0; j < 64; j++) {
        int je = (j + lane) & 63;
        float s[4], vv[4];
        #pragma unroll
        for (int ii = 0; ii < 4; ii++) s[ii] = sS[(i0 + ii) * 64 + je];
        #pragma unroll
        for (int dd = 0; dd < 4; dd++) vv[dd] = sA[je * 64 + d0 + dd];
        #pragma unroll
        for (int ii = 0; ii < 4; ii++)
            #pragma unroll
            for (int dd = 0; dd < 4; dd++)
                accO[ii][dd] += s[ii] * vv[dd];
    }
    #pragma unroll
    for (int ii = 0; ii < 4; ii++) {
        float4 ov = make_float4(accO[ii][0], accO[ii][1], accO[ii][2], accO[ii][3]);
        *reinterpret_cast<float4*>(
            &o[(size_t)(m0 + i0 + ii) * DMODEL + h * 64 + d0]) = ov;
    }
}

// ------------------------------- launcher -----------------------------------
extern "C" void kernel_launch(void* const* d_in, const int* in_sizes, int n_in,
                              void* d_out, int out_size) {
    (void)in_sizes; (void)n_in; (void)out_size;
    const float* input   = (const float*)d_in[0];
    const float* patch_w = (const float*)d_in[1];
    const float* patch_b = (const float*)d_in[2];
    const float* ln_g    = (const float*)d_in[3];
    const float* ln_b    = (const float*)d_in[4];
    const float* qkv_w   = (const float*)d_in[5];
    const float* qkv_b   = (const float*)d_in[6];
    const float* proj_w  = (const float*)d_in[7];
    const float* proj_b  = (const float*)d_in[8];
    const float* ff1_w   = (const float*)d_in[9];
    const float* ff1_b   = (const float*)d_in[10];
    const float* ff2_w   = (const float*)d_in[11];
    const float* ff2_b   = (const float*)d_in[12];
    float* out = (float*)d_out;

    float *x, *y, *z, *h, *qkv, *wT, *invf;
    cudaGetSymbolAddress((void**)&x,    g_x);
    cudaGetSymbolAddress((void**)&y,    g_y);
    cudaGetSymbolAddress((void**)&z,    g_z);
    cudaGetSymbolAddress((void**)&h,    g_h);
    cudaGetSymbolAddress((void**)&qkv,  g_qkv);
    cudaGetSymbolAddress((void**)&wT,   g_wT);
    cudaGetSymbolAddress((void**)&invf, g_invfreq);

    // prep
    build_invfreq_kernel<<<2, 192>>>(invf);
    transpose_pw_kernel<<<(DMODEL * DMODEL + 255) / 256, 256>>>(patch_w, wT);
    im2col_kernel<<<(MTOK * DMODEL / 4) / 256, 256>>>(input, h);

    // patch embed: y = im2col @ wT + patch_b
    sgemm_kernel<false, false><<<dim3(6, 128), 256>>>(h, wT, patch_b, nullptr, y,
                                                      MTOK, DMODEL, DMODEL);
    // x = LN(y) + PE   (identity #1)
    ln_pe_kernel<<<MTOK, 256>>>(y, ln_g, ln_b, invf, x);

    // ff block 1: h = gelu(x@ff1+b1); y = h@ff2+b2
    sgemm_kernel<true, false><<<dim3(24, 128), 256>>>(x, ff1_w, ff1_b, nullptr, h,
                                                      MTOK, FFDIM, DMODEL);
    sgemm_kernel<false, false><<<dim3(6, 128), 256>>>(h, ff2_w, ff2_b, nullptr, y,
                                                      MTOK, DMODEL, FFDIM);

    // attention on ff output
    sgemm_kernel<false, false><<<dim3(18, 128), 256>>>(y, qkv_w, qkv_b, nullptr, qkv,
                                                       MTOK, QKVDIM, DMODEL);
    attn_kernel<<<3072, 256>>>(qkv, y);
    // z = attn@proj + proj_b + x   (identity #2)
    sgemm_kernel<false, true><<<dim3(6, 128), 256>>>(y, proj_w, proj_b, x, z,
                                                     MTOK, DMODEL, DMODEL);

    // ff block 2 with residual into d_out
    sgemm_kernel<true, false><<<dim3(24, 128), 256>>>(z, ff1_w, ff1_b, nullptr, h,
                                                      MTOK, FFDIM, DMODEL);
    sgemm_kernel<false, true><<<dim3(6, 128), 256>>>(h, ff2_w, ff2_b, z, out,
                                                     MTOK, DMODEL, FFDIM);
}

// round 6
// speedup vs baseline: 2.0520x; 2.0520x over previous
#include <cuda_runtime.h>
#include <cuda_bf16.h>
#include <math.h>
#include <stdint.h>

// ---------------------------------------------------------------------------
// Problem constants
//   B=16, C=3, H=W=512, P=16 -> 16384 tokens; D=768, F=3072, NH=12, dh=64
// ---------------------------------------------------------------------------
#define MTOK   16384
#define DMODEL 768
#define FFDIM  3072
#define QKVDIM 2304

// ------------------------- scratch (device globals) ------------------------
__device__ float g_x[MTOK * DMODEL];     // LN+PE output (identity #1)
__device__ float g_y[MTOK * DMODEL];     // ff out / attn out
__device__ float g_z[MTOK * DMODEL];     // post-attn (identity #2)
__device__ float g_h[MTOK * FFDIM];      // im2col buffer, then FF hidden
__device__ float g_qkv[MTOK * QKVDIM];
__device__ float g_w1[FFDIM * DMODEL];   // ff1_w^T  [3072,768]  (N,K)
__device__ float g_w2[DMODEL * FFDIM];   // ff2_w^T  [768,3072]
__device__ float g_wq[QKVDIM * DMODEL];  // qkv_w^T  [2304,768]
__device__ float g_wp[DMODEL * DMODEL];  // proj_w^T [768,768]
__device__ float g_invfreq[DMODEL / 2];

// ------------------------------ PTX helpers ---------------------------------
__device__ __forceinline__ uint32_t smem_to_u32(const void* p) {
    uint32_t a;
    asm("{ .reg .u64 t; cvta.to.shared.u64 t, %1; cvt.u32.u64 %0, t; }"
        : "=r"(a) : "l"(p));
    return a;
}
#define CP_ASYNC16(dst, src) \
    asm volatile("cp.async.cg.shared.global [%0], [%1], 16;" \
        :: "r"(dst), "l"(src))
#define CP_COMMIT() asm volatile("cp.async.commit_group;" ::: "memory")
#define CP_WAIT1()  asm volatile("cp.async.wait_group 1;" ::: "memory")
#define CP_WAIT0()  asm volatile("cp.async.wait_group 0;" ::: "memory")

// D = A@B + D, tf32 operands, fp32 accum. A row-major 16x8, B col-major 8x8.
#define MMA_TF32(c, a, b) \
    asm volatile("mma.sync.aligned.m16n8k8.row.col.f32.tf32.tf32.f32 " \
        "{%0,%1,%2,%3}, {%4,%5,%6,%7}, {%8,%9}, {%0,%1,%2,%3};" \
        : "+f"((c)[0]), "+f"((c)[1]), "+f"((c)[2]), "+f"((c)[3]) \
        : "r"((a)[0]), "r"((a)[1]), "r"((a)[2]), "r"((a)[3]), \
          "r"((b)[0]), "r"((b)[1]))

__device__ __forceinline__ uint32_t cvt_tf32(float x) {
    uint32_t r;
    asm("cvt.rna.tf32.f32 %0, %1;" : "=r"(r) : "f"(x));
    return r;
}

// ------------------------------- small kernels ------------------------------
__device__ __forceinline__ float gelu_tanh(float x) {
    float x3 = x * x * x;
    return 0.5f * x * (1.f + tanhf(0.7978845608028654f * (x + 0.044715f * x3)));
}

__global__ void build_invfreq_kernel(float* inv) {
    int i = blockIdx.x * blockDim.x + threadIdx.x;
    if (i < DMODEL / 2)
        inv[i] = (float)exp(-(double)i * (2.0 / (double)DMODEL) * log(10000.0));
}

// out[c*R + r] = in[r*C + c]; R, C multiples of 32.
__global__ void transpose_kernel(const float* __restrict__ in,
                                 float* __restrict__ out, int R, int C) {
    __shared__ float t[32][33];
    int bx = blockIdx.x * 32, by = blockIdx.y * 32;
    int x = bx + threadIdx.x;
    #pragma unroll
    for (int j = 0; j < 32; j += 8)
        t[threadIdx.y + j][threadIdx.x] = in[(size_t)(by + threadIdx.y + j) * C + x];
    __syncthreads();
    int xo = by + threadIdx.x;
    #pragma unroll
    for (int j = 0; j < 32; j += 8)
        out[(size_t)(bx + threadIdx.y + j) * R + xo] = t[threadIdx.x][threadIdx.y + j];
}

__global__ void im2col_kernel(const float* __restrict__ in, float* __restrict__ A) {
    int idx = blockIdx.x * blockDim.x + threadIdx.x;
    int m = idx / 192;
    int k = (idx % 192) * 4;
    int b = m >> 10, n = m & 1023;
    int hp = n >> 5, wp = n & 31;
    int c = k >> 8, rem = k & 255;
    int p = rem >> 4, q = rem & 15;
    const float* src = in + ((((size_t)b * 3 + c) * 512) + (size_t)hp * 16 + p) * 512
                          + (size_t)wp * 16 + q;
    *reinterpret_cast<float4*>(&A[(size_t)m * DMODEL + k]) =
        *reinterpret_cast<const float4*>(src);
}

__global__ void ln_pe_kernel(const float* __restrict__ x, const float* __restrict__ gam,
                             const float* __restrict__ bet, const float* __restrict__ invfreq,
                             float* __restrict__ out) {
    __shared__ float ss[8], sq[8];
    int m = blockIdx.x;
    int t = threadIdx.x;
    const float* row = x + (size_t)m * DMODEL;
    float v0 = row[t], v1 = row[t + 256], v2 = row[t + 512];
    float s = v0 + v1 + v2;
    float q = v0 * v0 + v1 * v1 + v2 * v2;
    #pragma unroll
    for (int o = 16; o > 0; o >>= 1) {
        s += __shfl_down_sync(0xFFFFFFFFu, s, o);
        q += __shfl_down_sync(0xFFFFFFFFu, q, o);
    }
    int warp = t >> 5, lane = t & 31;
    if (lane == 0) { ss[warp] = s; sq[warp] = q; }
    __syncthreads();
    if (t == 0) {
        float S = 0.f, Q = 0.f;
        #pragma unroll
        for (int i = 0; i < 8; i++) { S += ss[i]; Q += sq[i]; }
        float mean = S * (1.f / 768.f);
        float var = Q * (1.f / 768.f) - mean * mean;
        ss[0] = mean;
        sq[0] = rsqrtf(var + 1e-5f);
    }
    __syncthreads();
    float mean = ss[0], rstd = sq[0];
    int n = m & 1023;
    float vals[3] = {v0, v1, v2};
    #pragma unroll
    for (int e = 0; e < 3; e++) {
        int d = t + e * 256;
        float ang = (float)n * invfreq[d >> 1];
        float pe = (d & 1) ? cosf(ang) : sinf(ang);
        out[(size_t)m * DMODEL + d] = (vals[e] - mean) * rstd * gam[d] + bet[d] + pe;
    }
}

// ---------------------- tf32 mma.sync GEMM ----------------------------------
// C[M,N] = A[M,K] @ Bw^T, Bw is [N,K] row-major (K contiguous).
// 128x128 tile, kTile=32, 256 threads = 8 warps (2 x 4), warp tile 64x32.
// Smem fp32 with pad-36 stride (conflict-free fragment loads), cp.async
// double-buffered. Epilogue: +bias, optional GELU, optional +res.
// Requires M%128==0, N%128==0, K%32==0.
#define GMEM_TILE_F   4608            // 128 * 36 floats
#define GEMM_SMEM_BYTES (4 * GMEM_TILE_F * 4)   // 73728 B

template <bool GELU, bool RES>
__global__ __launch_bounds__(256, 2)
void gemm_mma(const float* __restrict__ A, const float* __restrict__ Bw,
              const float* __restrict__ bias, const float* __restrict__ res,
              float* __restrict__ C, int M, int N, int K) {
    extern __shared__ float sm[];
    float* bufA[2] = { sm,                sm + 2 * GMEM_TILE_F };
    float* bufB[2] = { sm + GMEM_TILE_F,  sm + 3 * GMEM_TILE_F };

    const int tid  = threadIdx.x;
    const int m0   = blockIdx.y * 128;
    const int n0   = blockIdx.x * 128;
    const int lane = tid & 31, wid = tid >> 5;
    const int warpM = wid >> 2, warpN = wid & 3;
    const int g = lane >> 2, q = lane & 3;

    // tile-load geometry: each thread does 4 A + 4 B cp.asyncs of 16B
    const int r0 = tid >> 3;            // 0..31
    const int c4 = (tid & 7) * 4;       // 0..28
    uint32_t saA[2], saB[2];
    saA[0] = smem_to_u32(bufA[0]); saA[1] = smem_to_u32(bufA[1]);
    saB[0] = smem_to_u32(bufB[0]); saB[1] = smem_to_u32(bufB[1]);

    float acc[4][4][4];
    #pragma unroll
    for (int i = 0; i < 4; i++)
        #pragma unroll
        for (int j = 0; j < 4; j++)
            #pragma unroll
            for (int k = 0; k < 4; k++) acc[i][j][k] = 0.f;

    auto load_tile = [&](int buf, int k0) {
        #pragma unroll
        for (int i = 0; i < 4; i++) {
            int r = r0 + i * 32;
            CP_ASYNC16(saA[buf] + (uint32_t)(r * 36 + c4) * 4,
                       A + (size_t)(m0 + r) * K + k0 + c4);
            CP_ASYNC16(saB[buf] + (uint32_t)(r * 36 + c4) * 4,
                       Bw + (size_t)(n0 + r) * K + k0 + c4);
        }
    };

    const int nsteps = K >> 5;
    load_tile(0, 0);
    CP_COMMIT();

    for (int s = 0; s < nsteps; s++) {
        const int buf = s & 1;
        if (s + 1 < nsteps) {
            load_tile(buf ^ 1, (s + 1) * 32);
            CP_COMMIT();
            CP_WAIT1();
        } else {
            CP_WAIT0();
        }
        __syncthreads();

        const float* As = bufA[buf];
        const float* Bs = bufB[buf];
        #pragma unroll
        for (int k8 = 0; k8 < 4; k8++) {
            const int kq = k8 * 8 + q;
            uint32_t af[4][4], bf[4][2];
            #pragma unroll
            for (int mt = 0; mt < 4; mt++) {
                const int rm = warpM * 64 + mt * 16 + g;
                af[mt][0] = cvt_tf32(As[rm * 36 + kq]);
                af[mt][1] = cvt_tf32(As[(rm + 8) * 36 + kq]);
                af[mt][2] = cvt_tf32(As[rm * 36 + kq + 4]);
                af[mt][3] = cvt_tf32(As[(rm + 8) * 36 + kq + 4]);
            }
            #pragma unroll
            for (int nt = 0; nt < 4; nt++) {
                const int rn = warpN * 32 + nt * 8 + g;
                bf[nt][0] = cvt_tf32(Bs[rn * 36 + kq]);
                bf[nt][1] = cvt_tf32(Bs[rn * 36 + kq + 4]);
            }
            #pragma unroll
            for (int mt = 0; mt < 4; mt++)
                #pragma unroll
                for (int nt = 0; nt < 4; nt++)
                    MMA_TF32(acc[mt][nt], af[mt], bf[nt]);
        }
        __syncthreads();
    }

    // epilogue: c0,c1 -> (row g, cols 2q,2q+1); c2,c3 -> row g+8
    #pragma unroll
    for (int mt = 0; mt < 4; mt++) {
        #pragma unroll
        for (int half = 0; half < 2; half++) {
            const int row = m0 + warpM * 64 + mt * 16 + g + half * 8;
            float* crow = C + (size_t)row * N;
            const float* rrow = RES ? (res + (size_t)row * N) : nullptr;
            #pragma unroll
            for (int nt = 0; nt < 4; nt++) {
                const int col = n0 + warpN * 32 + nt * 8 + 2 * q;
                float v0 = acc[mt][nt][half * 2 + 0] + bias[col];
                float v1 = acc[mt][nt][half * 2 + 1] + bias[col + 1];
                if (GELU) { v0 = gelu_tanh(v0); v1 = gelu_tanh(v1); }
                if (RES)  { v0 += rrow[col]; v1 += rrow[col + 1]; }
                *reinterpret_cast<float2*>(&crow[col]) = make_float2(v0, v1);
            }
        }
    }
}

// --------------------------- window attention (fp32) ------------------------
__global__ __launch_bounds__(256)
void attn_kernel(const float* __restrict__ qkv, float* __restrict__ o) {
    __shared__ float sA[64 * 64];
    __shared__ float sK[64 * 64];
    __shared__ float sS[64 * 64];

    int wh = blockIdx.x;
    int h = wh % 12;
    int w = wh / 12;
    int m0 = (w >> 4) * 1024 + (w & 15) * 64;

    int tid = threadIdx.x;
    int lane = tid & 31;
    const float* base = qkv + (size_t)m0 * QKVDIM;
    int qoff = h * 64, koff = 768 + h * 64, voff = 1536 + h * 64;

    for (int u = tid; u < 1024; u += 256) {
        int r = u >> 4;
        int c4 = (u & 15) << 2;
        *reinterpret_cast<float4*>(&sA[r * 64 + c4]) =
            *reinterpret_cast<const float4*>(&base[(size_t)r * QKVDIM + qoff + c4]);
        *reinterpret_cast<float4*>(&sK[r * 64 + c4]) =
            *reinterpret_cast<const float4*>(&base[(size_t)r * QKVDIM + koff + c4]);
    }
    __syncthreads();

    int i0 = (tid >> 4) << 2;
    int j0 = (tid & 15) << 2;
    {
        float accS[4][4] = {};
        for (int kk = 0; kk < 64; kk++) {
            int ke = (kk + lane) & 63;
            float a[4], b[4];
            #pragma unroll
            for (int ii = 0; ii < 4; ii++) a[ii] = sA[(i0 + ii) * 64 + ke];
            #pragma unroll
            for (int jj = 0; jj < 4; jj++) b[jj] = sK[(j0 + jj) * 64 + ke];
            #pragma unroll
            for (int ii = 0; ii < 4; ii++)
                #pragma unroll
                for (int jj = 0; jj < 4; jj++)
                    accS[ii][jj] += a[ii] * b[jj];
        }
        #pragma unroll
        for (int ii = 0; ii < 4; ii++)
            #pragma unroll
            for (int jj = 0; jj < 4; jj++)
                sS[(i0 + ii) * 64 + (j0 + jj)] = accS[ii][jj] * 0.125f;
    }
    __syncthreads();

    if (tid < 64) {
        int i = tid;
        float mx = -1e30f;
        for (int j = 0; j < 64; j++)
            mx = fmaxf(mx, sS[i * 64 + ((j + tid) & 63)]);
        float sum = 0.f;
        for (int j = 0; j < 64; j++) {
            int jj = (j + tid) & 63;
            float e = expf(sS[i * 64 + jj] - mx);
            sS[i * 64 + jj] = e;
            sum += e;
        }
        float invs = 1.f / sum;
        for (int j = 0; j < 64; j++) {
            int jj = (j + tid) & 63;
            sS[i * 64 + jj] *= invs;
        }
    }
    for (int u = tid; u < 1024; u += 256) {
        int r = u >> 4;
        int c4 = (u & 15) << 2;
        *reinterpret_cast<float4*>(&sA[r * 64 + c4]) =
            *reinterpret_cast<const float4*>(&base[(size_t)r * QKVDIM + voff + c4]);
    }
    __syncthreads();

    int d0 = j0;
    float accO[4][4] = {};
    for (int j = 0; j < 64; j++) {
        int je = (j + lane) & 63;
        float s[4], vv[4];
        #pragma unroll
        for (int ii = 0; ii < 4; ii++) s[ii] = sS[(i0 + ii) * 64 + je];
        #pragma unroll
        for (int dd = 0; dd < 4; dd++) vv[dd] = sA[je * 64 + d0 + dd];
        #pragma unroll
        for (int ii = 0; ii < 4; ii++)
            #pragma unroll
            for (int dd = 0; dd < 4; dd++)
                accO[ii][dd] += s[ii] * vv[dd];
    }
    #pragma unroll
    for (int ii = 0; ii < 4; ii++) {
        float4 ov = make_float4(accO[ii][0], accO[ii][1], accO[ii][2], accO[ii][3]);
        *reinterpret_cast<float4*>(
            &o[(size_t)(m0 + i0 + ii) * DMODEL + h * 64 + d0]) = ov;
    }
}

// ------------------------------- launcher -----------------------------------
extern "C" void kernel_launch(void* const* d_in, const int* in_sizes, int n_in,
                              void* d_out, int out_size) {
    (void)in_sizes; (void)n_in; (void)out_size;
    const float* input   = (const float*)d_in[0];
    const float* patch_w = (const float*)d_in[1];
    const float* patch_b = (const float*)d_in[2];
    const float* ln_g    = (const float*)d_in[3];
    const float* ln_b    = (const float*)d_in[4];
    const float* qkv_w   = (const float*)d_in[5];
    const float* qkv_b   = (const float*)d_in[6];
    const float* proj_w  = (const float*)d_in[7];
    const float* proj_b  = (const float*)d_in[8];
    const float* ff1_w   = (const float*)d_in[9];
    const float* ff1_b   = (const float*)d_in[10];
    const float* ff2_w   = (const float*)d_in[11];
    const float* ff2_b   = (const float*)d_in[12];
    float* out = (float*)d_out;

    float *x, *y, *z, *h, *qkv, *w1, *w2, *wq, *wp, *invf;
    cudaGetSymbolAddress((void**)&x,    g_x);
    cudaGetSymbolAddress((void**)&y,    g_y);
    cudaGetSymbolAddress((void**)&z,    g_z);
    cudaGetSymbolAddress((void**)&h,    g_h);
    cudaGetSymbolAddress((void**)&qkv,  g_qkv);
    cudaGetSymbolAddress((void**)&w1,   g_w1);
    cudaGetSymbolAddress((void**)&w2,   g_w2);
    cudaGetSymbolAddress((void**)&wq,   g_wq);
    cudaGetSymbolAddress((void**)&wp,   g_wp);
    cudaGetSymbolAddress((void**)&invf, g_invfreq);

    cudaFuncSetAttribute((const void*)gemm_mma<false, false>,
                         cudaFuncAttributeMaxDynamicSharedMemorySize, GEMM_SMEM_BYTES);
    cudaFuncSetAttribute((const void*)gemm_mma<true, false>,
                         cudaFuncAttributeMaxDynamicSharedMemorySize, GEMM_SMEM_BYTES);
    cudaFuncSetAttribute((const void*)gemm_mma<false, true>,
                         cudaFuncAttributeMaxDynamicSharedMemorySize, GEMM_SMEM_BYTES);

    // prep
    build_invfreq_kernel<<<2, 192>>>(invf);
    transpose_kernel<<<dim3(96, 24), dim3(32, 8)>>>(ff1_w, w1, DMODEL, FFDIM);
    transpose_kernel<<<dim3(24, 96), dim3(32, 8)>>>(ff2_w, w2, FFDIM, DMODEL);
    transpose_kernel<<<dim3(72, 24), dim3(32, 8)>>>(qkv_w, wq, DMODEL, QKVDIM);
    transpose_kernel<<<dim3(24, 24), dim3(32, 8)>>>(proj_w, wp, DMODEL, DMODEL);
    im2col_kernel<<<(MTOK * DMODEL / 4) / 256, 256>>>(input, h);

    // patch embed: y = im2col @ patch_w^T + patch_b  (patch_w already [N,K])
    gemm_mma<false, false><<<dim3(6, 128), 256, GEMM_SMEM_BYTES>>>(
        h, patch_w, patch_b, nullptr, y, MTOK, DMODEL, DMODEL);
    // x = LN(y) + PE  (identity #1)
    ln_pe_kernel<<<MTOK, 256>>>(y, ln_g, ln_b, invf, x);

    // ff block 1
    gemm_mma<true, false><<<dim3(24, 128), 256, GEMM_SMEM_BYTES>>>(
        x, w1, ff1_b, nullptr, h, MTOK, FFDIM, DMODEL);
    gemm_mma<false, false><<<dim3(6, 128), 256, GEMM_SMEM_BYTES>>>(
        h, w2, ff2_b, nullptr, y, MTOK, DMODEL, FFDIM);

    // attention
    gemm_mma<false, false><<<dim3(18, 128), 256, GEMM_SMEM_BYTES>>>(
        y, wq, qkv_b, nullptr, qkv, MTOK, QKVDIM, DMODEL);
    attn_kernel<<<3072, 256>>>(qkv, y);
    gemm_mma<false, true><<<dim3(6, 128), 256, GEMM_SMEM_BYTES>>>(
        y, wp, proj_b, x, z, MTOK, DMODEL, DMODEL);

    // ff block 2 (residual into d_out)
    gemm_mma<true, false><<<dim3(24, 128), 256, GEMM_SMEM_BYTES>>>(
        z, w1, ff1_b, nullptr, h, MTOK, FFDIM, DMODEL);
    gemm_mma<false, true><<<dim3(6, 128), 256, GEMM_SMEM_BYTES>>>(
        h, w2, ff2_b, z, out, MTOK, DMODEL, FFDIM);
}

// round 7
// speedup vs baseline: 5.3503x; 2.6073x over previous
#include <cuda_runtime.h>
#include <cuda_fp16.h>
#include <math.h>
#include <stdint.h>

// ---------------------------------------------------------------------------
// B=16, C=3, H=W=512, P=16 -> 16384 tokens; D=768, F=3072, NH=12, dh=64
// ---------------------------------------------------------------------------
#define MTOK   16384
#define DMODEL 768
#define FFDIM  3072
#define QKVDIM 2304

// ------------------------- scratch (device globals) ------------------------
__device__ float  g_x[MTOK * DMODEL];       // identity #1 (fp32)
__device__ float  g_y[MTOK * DMODEL];       // patch-embed out (fp32)
__device__ float  g_z[MTOK * DMODEL];       // identity #2 (fp32)
__device__ float  g_qkv[MTOK * QKVDIM];     // qkv (fp32, attention input)
__device__ __half g_h16[MTOK * FFDIM];      // im2col, then FF hidden (fp16)
__device__ __half g_actA[MTOK * DMODEL];    // fp16 activation ping
__device__ __half g_actB[MTOK * DMODEL];    // fp16 activation pong
__device__ __half g_w1h[FFDIM * DMODEL];    // ff1_w^T  [N,K] fp16
__device__ __half g_w2h[DMODEL * FFDIM];    // ff2_w^T
__device__ __half g_wqh[QKVDIM * DMODEL];   // qkv_w^T
__device__ __half g_wph[DMODEL * DMODEL];   // proj_w^T
__device__ __half g_pwh[DMODEL * DMODEL];   // patch_w (already [N,K]) fp16
__device__ float  g_invfreq[DMODEL / 2];

// ------------------------------ PTX helpers ---------------------------------
__device__ __forceinline__ uint32_t smem_to_u32(const void* p) {
    uint32_t a;
    asm("{ .reg .u64 t; cvta.to.shared.u64 t, %1; cvt.u32.u64 %0, t; }"
        : "=r"(a) : "l"(p));
    return a;
}
#define CP_ASYNC16(dst, src) \
    asm volatile("cp.async.cg.shared.global [%0], [%1], 16;" \
        :: "r"(dst), "l"(src))
#define CP_COMMIT() asm volatile("cp.async.commit_group;" ::: "memory")
#define CP_WAIT1()  asm volatile("cp.async.wait_group 1;" ::: "memory")
#define CP_WAIT0()  asm volatile("cp.async.wait_group 0;" ::: "memory")

#define LDMATRIX_X4(r0, r1, r2, r3, addr) \
    asm volatile("ldmatrix.sync.aligned.m8n8.x4.shared.b16 {%0,%1,%2,%3}, [%4];" \
        : "=r"(r0), "=r"(r1), "=r"(r2), "=r"(r3) : "r"(addr))

#define MMA_F16(c, a, b) \
    asm volatile("mma.sync.aligned.m16n8k16.row.col.f32.f16.f16.f32 " \
        "{%0,%1,%2,%3}, {%4,%5,%6,%7}, {%8,%9}, {%0,%1,%2,%3};" \
        : "+f"((c)[0]), "+f"((c)[1]), "+f"((c)[2]), "+f"((c)[3]) \
        : "r"((a)[0]), "r"((a)[1]), "r"((a)[2]), "r"((a)[3]), \
          "r"((b)[0]), "r"((b)[1]))

// ------------------------------- small kernels ------------------------------
__device__ __forceinline__ float gelu_tanh(float x) {
    float x3 = x * x * x;
    return 0.5f * x * (1.f + tanhf(0.7978845608028654f * (x + 0.044715f * x3)));
}

__global__ void build_invfreq_kernel(float* inv) {
    int i = blockIdx.x * blockDim.x + threadIdx.x;
    if (i < DMODEL / 2)
        inv[i] = (float)exp(-(double)i * (2.0 / (double)DMODEL) * log(10000.0));
}

// out[c*R + r] = (half)in[r*C + c]
__global__ void transpose_h_kernel(const float* __restrict__ in,
                                   __half* __restrict__ out, int R, int C) {
    __shared__ float t[32][33];
    int bx = blockIdx.x * 32, by = blockIdx.y * 32;
    int x = bx + threadIdx.x;
    #pragma unroll
    for (int j = 0; j < 32; j += 8)
        t[threadIdx.y + j][threadIdx.x] = in[(size_t)(by + threadIdx.y + j) * C + x];
    __syncthreads();
    int xo = by + threadIdx.x;
    #pragma unroll
    for (int j = 0; j < 32; j += 8)
        out[(size_t)(bx + threadIdx.y + j) * R + xo] =
            __float2half(t[threadIdx.x][threadIdx.y + j]);
}

__global__ void f2h_kernel(const float* __restrict__ in, __half* __restrict__ out,
                           int n) {
    int i = blockIdx.x * blockDim.x + threadIdx.x;
    if (i * 2 < n) {
        float2 v = *reinterpret_cast<const float2*>(&in[i * 2]);
        *reinterpret_cast<__half2*>(&out[i * 2]) = __floats2half2_rn(v.x, v.y);
    }
}

__global__ void im2col_h_kernel(const float* __restrict__ in,
                                __half* __restrict__ A) {
    int idx = blockIdx.x * blockDim.x + threadIdx.x;
    int m = idx / 192;
    int k = (idx % 192) * 4;
    int b = m >> 10, n = m & 1023;
    int hp = n >> 5, wp = n & 31;
    int c = k >> 8, rem = k & 255;
    int p = rem >> 4, q = rem & 15;
    const float* src = in + ((((size_t)b * 3 + c) * 512) + (size_t)hp * 16 + p) * 512
                          + (size_t)wp * 16 + q;
    float4 v = *reinterpret_cast<const float4*>(src);
    __half2* dst = reinterpret_cast<__half2*>(&A[(size_t)m * DMODEL + k]);
    dst[0] = __floats2half2_rn(v.x, v.y);
    dst[1] = __floats2half2_rn(v.z, v.w);
}

__global__ void ln_pe_kernel(const float* __restrict__ x, const float* __restrict__ gam,
                             const float* __restrict__ bet, const float* __restrict__ invfreq,
                             float* __restrict__ out, __half* __restrict__ outh) {
    __shared__ float ss[8], sq[8];
    int m = blockIdx.x;
    int t = threadIdx.x;
    const float* row = x + (size_t)m * DMODEL;
    float v0 = row[t], v1 = row[t + 256], v2 = row[t + 512];
    float s = v0 + v1 + v2;
    float q = v0 * v0 + v1 * v1 + v2 * v2;
    #pragma unroll
    for (int o = 16; o > 0; o >>= 1) {
        s += __shfl_down_sync(0xFFFFFFFFu, s, o);
        q += __shfl_down_sync(0xFFFFFFFFu, q, o);
    }
    int warp = t >> 5, lane = t & 31;
    if (lane == 0) { ss[warp] = s; sq[warp] = q; }
    __syncthreads();
    if (t == 0) {
        float S = 0.f, Q = 0.f;
        #pragma unroll
        for (int i = 0; i < 8; i++) { S += ss[i]; Q += sq[i]; }
        float mean = S * (1.f / 768.f);
        float var = Q * (1.f / 768.f) - mean * mean;
        ss[0] = mean;
        sq[0] = rsqrtf(var + 1e-5f);
    }
    __syncthreads();
    float mean = ss[0], rstd = sq[0];
    int n = m & 1023;
    float vals[3] = {v0, v1, v2};
    #pragma unroll
    for (int e = 0; e < 3; e++) {
        int d = t + e * 256;
        float ang = (float)n * invfreq[d >> 1];
        float pe = (d & 1) ? cosf(ang) : sinf(ang);
        float r = (vals[e] - mean) * rstd * gam[d] + bet[d] + pe;
        out[(size_t)m * DMODEL + d] = r;
        outh[(size_t)m * DMODEL + d] = __float2half(r);
    }
}

// ---------------------- fp16 mma.sync GEMM ----------------------------------
// C = A[M,K] @ Bw^T (+bias, opt GELU, opt +res). Bw is [N,K] fp16, K contig.
// 128x128x64 tile, 256 threads = 8 warps (2x4), warp tile 64x32.
// Smem: XOR-swizzled 128B rows, cp.async double buffer, ldmatrix fragments.
// Writes fp32 C32 (if non-null) and/or fp16 C16 (if non-null).
#define GEMM_SMEM_BYTES 65536

template <bool GELU, bool RES>
__global__ __launch_bounds__(256, 2)
void gemm_h(const __half* __restrict__ A, const __half* __restrict__ Bw,
            const float* __restrict__ bias, const float* __restrict__ res,
            float* __restrict__ C32, __half* __restrict__ C16,
            int M, int N, int K) {
    extern __shared__ char smraw[];
    const uint32_t sb = smem_to_u32(smraw);
    const uint32_t sA[2] = { sb, sb + 16384 };
    const uint32_t sB[2] = { sb + 32768, sb + 49152 };

    const int tid = threadIdx.x;
    const int m0 = blockIdx.y * 128;
    const int n0 = blockIdx.x * 128;
    const int lane = tid & 31, wid = tid >> 5;
    const int warpM = wid >> 2, warpN = wid & 3;
    const int g = lane >> 2, q = lane & 3;
    const int sel = lane >> 3, rr = lane & 7;

    float acc[4][4][4];
    #pragma unroll
    for (int i = 0; i < 4; i++)
        #pragma unroll
        for (int j = 0; j < 4; j++)
            #pragma unroll
            for (int k = 0; k < 4; k++) acc[i][j][k] = 0.f;

    // cp.async mapping: 1024 16B-chunks per matrix, 4 per thread
    int crow[4], cchk[4];
    #pragma unroll
    for (int i = 0; i < 4; i++) {
        int idx = tid + i * 256;
        crow[i] = idx >> 3;
        cchk[i] = idx & 7;
    }

    auto load_tile = [&](int buf, int k0) {
        #pragma unroll
        for (int i = 0; i < 4; i++) {
            int r = crow[i], c = cchk[i];
            uint32_t sw = (uint32_t)(r * 128 + ((c ^ (r & 7)) << 4));
            CP_ASYNC16(sA[buf] + sw, A + (size_t)(m0 + r) * K + k0 + c * 8);
            CP_ASYNC16(sB[buf] + sw, Bw + (size_t)(n0 + r) * K + k0 + c * 8);
        }
    };

    // ldmatrix row geometry (fixed per thread)
    int mrow[4], nrow[2];
    #pragma unroll
    for (int mt = 0; mt < 4; mt++)
        mrow[mt] = warpM * 64 + mt * 16 + ((sel & 1) << 3) + rr;
    #pragma unroll
    for (int np = 0; np < 2; np++)
        nrow[np] = warpN * 32 + np * 16 + ((sel >> 1) << 3) + rr;
    const int achk = sel >> 1;      // chunk offset for A
    const int bchk = sel & 1;       // chunk offset for B

    const int nsteps = K >> 6;
    load_tile(0, 0);
    CP_COMMIT();

    for (int s = 0; s < nsteps; s++) {
        const int buf = s & 1;
        if (s + 1 < nsteps) {
            load_tile(buf ^ 1, (s + 1) * 64);
            CP_COMMIT();
            CP_WAIT1();
        } else {
            CP_WAIT0();
        }
        __syncthreads();

        #pragma unroll
        for (int step = 0; step < 4; step++) {
            const int c0 = step * 2;
            uint32_t af[4][4], bf[4][2];
            #pragma unroll
            for (int mt = 0; mt < 4; mt++) {
                int r = mrow[mt];
                uint32_t addr = sA[buf] + r * 128 + (((c0 + achk) ^ (r & 7)) << 4);
                LDMATRIX_X4(af[mt][0], af[mt][1], af[mt][2], af[mt][3], addr);
            }
            #pragma unroll
            for (int np = 0; np < 2; np++) {
                int r = nrow[np];
                uint32_t addr = sB[buf] + r * 128 + (((c0 + bchk) ^ (r & 7)) << 4);
                LDMATRIX_X4(bf[2 * np][0], bf[2 * np][1],
                            bf[2 * np + 1][0], bf[2 * np + 1][1], addr);
            }
            #pragma unroll
            for (int mt = 0; mt < 4; mt++)
                #pragma unroll
                for (int nt = 0; nt < 4; nt++)
                    MMA_F16(acc[mt][nt], af[mt], bf[nt]);
        }
        __syncthreads();
    }

    // epilogue
    #pragma unroll
    for (int mt = 0; mt < 4; mt++) {
        #pragma unroll
        for (int half = 0; half < 2; half++) {
            const int row = m0 + warpM * 64 + mt * 16 + g + half * 8;
            float* c32row = C32 ? (C32 + (size_t)row * N) : nullptr;
            __half* c16row = C16 ? (C16 + (size_t)row * N) : nullptr;
            const float* rrow = RES ? (res + (size_t)row * N) : nullptr;
            #pragma unroll
            for (int nt = 0; nt < 4; nt++) {
                const int col = n0 + warpN * 32 + nt * 8 + 2 * q;
                float v0 = acc[mt][nt][half * 2 + 0] + bias[col];
                float v1 = acc[mt][nt][half * 2 + 1] + bias[col + 1];
                if (GELU) { v0 = gelu_tanh(v0); v1 = gelu_tanh(v1); }
                if (RES)  { v0 += rrow[col]; v1 += rrow[col + 1]; }
                if (c32row)
                    *reinterpret_cast<float2*>(&c32row[col]) = make_float2(v0, v1);
                if (c16row)
                    *reinterpret_cast<__half2*>(&c16row[col]) = __floats2half2_rn(v0, v1);
            }
        }
    }
}

// --------------------------- window attention (fp32) ------------------------
__global__ __launch_bounds__(256)
void attn_kernel(const float* __restrict__ qkv, __half* __restrict__ o) {
    __shared__ float sA[64 * 64];
    __shared__ float sK[64 * 64];
    __shared__ float sS[64 * 64];

    int wh = blockIdx.x;
    int h = wh % 12;
    int w = wh / 12;
    int m0 = (w >> 4) * 1024 + (w & 15) * 64;

    int tid = threadIdx.x;
    int lane = tid & 31;
    const float* base = qkv + (size_t)m0 * QKVDIM;
    int qoff = h * 64, koff = 768 + h * 64, voff = 1536 + h * 64;

    for (int u = tid; u < 1024; u += 256) {
        int r = u >> 4;
        int c4 = (u & 15) << 2;
        *reinterpret_cast<float4*>(&sA[r * 64 + c4]) =
            *reinterpret_cast<const float4*>(&base[(size_t)r * QKVDIM + qoff + c4]);
        *reinterpret_cast<float4*>(&sK[r * 64 + c4]) =
            *reinterpret_cast<const float4*>(&base[(size_t)r * QKVDIM + koff + c4]);
    }
    __syncthreads();

    int i0 = (tid >> 4) << 2;
    int j0 = (tid & 15) << 2;
    {
        float accS[4][4] = {};
        for (int kk = 0; kk < 64; kk++) {
            int ke = (kk + lane) & 63;
            float a[4], b[4];
            #pragma unroll
            for (int ii = 0; ii < 4; ii++) a[ii] = sA[(i0 + ii) * 64 + ke];
            #pragma unroll
            for (int jj = 0; jj < 4; jj++) b[jj] = sK[(j0 + jj) * 64 + ke];
            #pragma unroll
            for (int ii = 0; ii < 4; ii++)
                #pragma unroll
                for (int jj = 0; jj < 4; jj++)
                    accS[ii][jj] += a[ii] * b[jj];
        }
        #pragma unroll
        for (int ii = 0; ii < 4; ii++)
            #pragma unroll
            for (int jj = 0; jj < 4; jj++)
                sS[(i0 + ii) * 64 + (j0 + jj)] = accS[ii][jj] * 0.125f;
    }
    __syncthreads();

    if (tid < 64) {
        int i = tid;
        float mx = -1e30f;
        for (int j = 0; j < 64; j++)
            mx = fmaxf(mx, sS[i * 64 + ((j + tid) & 63)]);
        float sum = 0.f;
        for (int j = 0; j < 64; j++) {
            int jj = (j + tid) & 63;
            float e = expf(sS[i * 64 + jj] - mx);
            sS[i * 64 + jj] = e;
            sum += e;
        }
        float invs = 1.f / sum;
        for (int j = 0; j < 64; j++) {
            int jj = (j + tid) & 63;
            sS[i * 64 + jj] *= invs;
        }
    }
    for (int u = tid; u < 1024; u += 256) {
        int r = u >> 4;
        int c4 = (u & 15) << 2;
        *reinterpret_cast<float4*>(&sA[r * 64 + c4]) =
            *reinterpret_cast<const float4*>(&base[(size_t)r * QKVDIM + voff + c4]);
    }
    __syncthreads();

    int d0 = j0;
    float accO[4][4] = {};
    for (int j = 0; j < 64; j++) {
        int je = (j + lane) & 63;
        float s[4], vv[4];
        #pragma unroll
        for (int ii = 0; ii < 4; ii++) s[ii] = sS[(i0 + ii) * 64 + je];
        #pragma unroll
        for (int dd = 0; dd < 4; dd++) vv[dd] = sA[je * 64 + d0 + dd];
        #pragma unroll
        for (int ii = 0; ii < 4; ii++)
            #pragma unroll
            for (int dd = 0; dd < 4; dd++)
                accO[ii][dd] += s[ii] * vv[dd];
    }
    #pragma unroll
    for (int ii = 0; ii < 4; ii++) {
        __half* orow = o + (size_t)(m0 + i0 + ii) * DMODEL + h * 64 + d0;
        *reinterpret_cast<__half2*>(orow) = __floats2half2_rn(accO[ii][0], accO[ii][1]);
        *reinterpret_cast<__half2*>(orow + 2) = __floats2half2_rn(accO[ii][2], accO[ii][3]);
    }
}

// ------------------------------- launcher -----------------------------------
extern "C" void kernel_launch(void* const* d_in, const int* in_sizes, int n_in,
                              void* d_out, int out_size) {
    (void)in_sizes; (void)n_in; (void)out_size;
    const float* input   = (const float*)d_in[0];
    const float* patch_w = (const float*)d_in[1];
    const float* patch_b = (const float*)d_in[2];
    const float* ln_g    = (const float*)d_in[3];
    const float* ln_b    = (const float*)d_in[4];
    const float* qkv_w   = (const float*)d_in[5];
    const float* qkv_b   = (const float*)d_in[6];
    const float* proj_w  = (const float*)d_in[7];
    const float* proj_b  = (const float*)d_in[8];
    const float* ff1_w   = (const float*)d_in[9];
    const float* ff1_b   = (const float*)d_in[10];
    const float* ff2_w   = (const float*)d_in[11];
    const float* ff2_b   = (const float*)d_in[12];
    float* out = (float*)d_out;

    float *x, *y, *z, *qkv, *invf;
    __half *h16, *actA, *actB, *w1h, *w2h, *wqh, *wph, *pwh;
    cudaGetSymbolAddress((void**)&x,    g_x);
    cudaGetSymbolAddress((void**)&y,    g_y);
    cudaGetSymbolAddress((void**)&z,    g_z);
    cudaGetSymbolAddress((void**)&qkv,  g_qkv);
    cudaGetSymbolAddress((void**)&h16,  g_h16);
    cudaGetSymbolAddress((void**)&actA, g_actA);
    cudaGetSymbolAddress((void**)&actB, g_actB);
    cudaGetSymbolAddress((void**)&w1h,  g_w1h);
    cudaGetSymbolAddress((void**)&w2h,  g_w2h);
    cudaGetSymbolAddress((void**)&wqh,  g_wqh);
    cudaGetSymbolAddress((void**)&wph,  g_wph);
    cudaGetSymbolAddress((void**)&pwh,  g_pwh);
    cudaGetSymbolAddress((void**)&invf, g_invfreq);

    cudaFuncSetAttribute((const void*)gemm_h<false, false>,
                         cudaFuncAttributeMaxDynamicSharedMemorySize, GEMM_SMEM_BYTES);
    cudaFuncSetAttribute((const void*)gemm_h<true, false>,
                         cudaFuncAttributeMaxDynamicSharedMemorySize, GEMM_SMEM_BYTES);
    cudaFuncSetAttribute((const void*)gemm_h<false, true>,
                         cudaFuncAttributeMaxDynamicSharedMemorySize, GEMM_SMEM_BYTES);

    // prep: PE table, fp16 weight transposes, patch_w convert, im2col
    build_invfreq_kernel<<<2, 192>>>(invf);
    transpose_h_kernel<<<dim3(96, 24), dim3(32, 8)>>>(ff1_w, w1h, DMODEL, FFDIM);
    transpose_h_kernel<<<dim3(24, 96), dim3(32, 8)>>>(ff2_w, w2h, FFDIM, DMODEL);
    transpose_h_kernel<<<dim3(72, 24), dim3(32, 8)>>>(qkv_w, wqh, DMODEL, QKVDIM);
    transpose_h_kernel<<<dim3(24, 24), dim3(32, 8)>>>(proj_w, wph, DMODEL, DMODEL);
    f2h_kernel<<<(DMODEL * DMODEL / 2 + 255) / 256, 256>>>(patch_w, pwh,
                                                           DMODEL * DMODEL);
    im2col_h_kernel<<<(MTOK * DMODEL / 4) / 256, 256>>>(input, h16);

    // patch embed -> y (fp32)
    gemm_h<false, false><<<dim3(6, 128), 256, GEMM_SMEM_BYTES>>>(
        h16, pwh, patch_b, nullptr, y, nullptr, MTOK, DMODEL, DMODEL);
    // LN + PE -> x (fp32 identity) + actA (fp16)
    ln_pe_kernel<<<MTOK, 256>>>(y, ln_g, ln_b, invf, x, actA);

    // ff block 1: h16 = gelu(actA @ w1h), actB = h16 @ w2h
    gemm_h<true, false><<<dim3(24, 128), 256, GEMM_SMEM_BYTES>>>(
        actA, w1h, ff1_b, nullptr, nullptr, h16, MTOK, FFDIM, DMODEL);
    gemm_h<false, false><<<dim3(6, 128), 256, GEMM_SMEM_BYTES>>>(
        h16, w2h, ff2_b, nullptr, nullptr, actB, MTOK, DMODEL, FFDIM);

    // attention: qkv (fp32) -> attn -> actA (fp16)
    gemm_h<false, false><<<dim3(18, 128), 256, GEMM_SMEM_BYTES>>>(
        actB, wqh, qkv_b, nullptr, qkv, nullptr, MTOK, QKVDIM, DMODEL);
    attn_kernel<<<3072, 256>>>(qkv, actA);
    // proj + residual(x) -> z (fp32) + actB (fp16)
    gemm_h<false, true><<<dim3(6, 128), 256, GEMM_SMEM_BYTES>>>(
        actA, wph, proj_b, x, z, actB, MTOK, DMODEL, DMODEL);

    // ff block 2 + residual(z) -> d_out
    gemm_h<true, false><<<dim3(24, 128), 256, GEMM_SMEM_BYTES>>>(
        actB, w1h, ff1_b, nullptr, nullptr, h16, MTOK, FFDIM, DMODEL);
    gemm_h<false, true><<<dim3(6, 128), 256, GEMM_SMEM_BYTES>>>(
        h16, w2h, ff2_b, z, out, nullptr, MTOK, DMODEL, FFDIM);
}